// round 13
// baseline (speedup 1.0000x reference)
#include <cuda_runtime.h>
#include <math.h>

#define NB    64
#define NL    512
#define ND    128
#define TOKS  32768          // B*L per stream
#define NTOK  65536          // 2*B*L
#define NHB   256            // 2*B*H attention batches

// ---------------- scratch (device globals; no allocation allowed) ----------------
__device__ int   g_cnt[NTOK * 2];
__device__ float g_W[ND * ND];
__device__ float g_biasT[ND];
__device__ float g_T2[513 * ND];
__device__ float g_X[(size_t)NTOK * ND];
__device__ float g_H[(size_t)NTOK * ND];
__device__ float g_QKV[(size_t)NTOK * 3 * ND];
__device__ float g_CTX[(size_t)NTOK * ND];
__device__ float g_FF[(size_t)NTOK * 4 * ND];
__device__ float g_WR[196608];   // pre-rounded weights: QKV | WO | FF1 | FF2

#define WR_QKV 0
#define WR_WO  49152
#define WR_FF1 65536
#define WR_FF2 131072

#define BUF_X    0
#define BUF_H    1
#define BUF_QKV  2
#define BUF_CTX  3
#define BUF_FF   4
__device__ __forceinline__ float* buf(int id) {
    switch (id) {
        case BUF_X:   return g_X;
        case BUF_H:   return g_H;
        case BUF_QKV: return g_QKV;
        case BUF_CTX: return g_CTX;
        default:      return g_FF;
    }
}

// fp32 -> tf32 (round to nearest)
__device__ __forceinline__ float f2tf(float x) {
    unsigned r;
    asm("cvt.rna.tf32.f32 %0, %1;" : "=r"(r) : "f"(x));
    return __uint_as_float(r);
}

__device__ __forceinline__ void mma_tf32(float* c, const unsigned* a, const unsigned* b) {
    asm volatile(
        "mma.sync.aligned.m16n8k8.row.col.f32.tf32.tf32.f32 "
        "{%0,%1,%2,%3}, {%4,%5,%6,%7}, {%8,%9}, {%0,%1,%2,%3};"
        : "+f"(c[0]), "+f"(c[1]), "+f"(c[2]), "+f"(c[3])
        : "r"(a[0]), "r"(a[1]), "r"(a[2]), "r"(a[3]), "r"(b[0]), "r"(b[1]));
}

__device__ __forceinline__ void cp_async16(float* smem_dst, const float* gsrc) {
    unsigned saddr = (unsigned)__cvta_generic_to_shared(smem_dst);
    asm volatile("cp.async.cg.shared.global [%0], [%1], 16;" :: "r"(saddr), "l"(gsrc));
}

// fast exact-gelu: Abramowitz-Stegun 7.1.26 erf (abs err 1.5e-7)
__device__ __forceinline__ float gelu_f(float x) {
    float z  = x * 0.70710678118654752f;
    float az = fabsf(z);
    float t  = __fdividef(1.f, fmaf(0.3275911f, az, 1.f));
    float p  = t * (0.254829592f + t * (-0.284496736f + t * (1.421413741f +
               t * (-1.453152027f + t * 1.061405429f))));
    float er = copysignf(1.f - p * __expf(-z * z), z);
    return 0.5f * x * (1.f + er);
}

// ---------------- precompute: round all 4 weight matrices in ONE launch ----------------
__global__ void k_rnd_all(const float* __restrict__ qkv, const float* __restrict__ wo,
                          const float* __restrict__ ff1, const float* __restrict__ ff2) {
    int i = blockIdx.x * 256 + threadIdx.x;      // 196608 total
    const float* s; int off;
    if (i < 49152)        { s = qkv; off = i; }
    else if (i < 65536)   { s = wo;  off = i - 49152; }
    else if (i < 131072)  { s = ff1; off = i - 65536; }
    else                  { s = ff2; off = i - 131072; }
    g_WR[i] = f2tf(s[off]);
}

// W = w2 @ proj_w (blocks 0..127) and biasT (block 128) in one launch
__global__ void k_Wb(const float* __restrict__ w2, const float* __restrict__ proj_w,
                     const float* __restrict__ b2, const float* __restrict__ proj_b) {
    int d = threadIdx.x;
    if (blockIdx.x < ND) {
        int k = blockIdx.x;
        float acc = 0.f;
        #pragma unroll 8
        for (int j = 0; j < ND; j++) acc += w2[k * ND + j] * proj_w[j * ND + d];
        g_W[k * ND + d] = acc;
    } else {
        float acc = proj_b[d];
        #pragma unroll 8
        for (int k = 0; k < ND; k++) acc += 2.f * b2[k] * proj_w[k * ND + d];
        g_biasT[d] = acc;
    }
}

__global__ void k_table(const float* __restrict__ w1, const float* __restrict__ b1) {
    __shared__ float h[ND];
    int c = blockIdx.x, d = threadIdx.x;
    h[d] = fmaxf((float)c * w1[d] + b1[d], 0.f);
    __syncthreads();
    float acc = 0.5f * g_biasT[d];
    #pragma unroll 8
    for (int k = 0; k < ND; k++) acc += h[k] * g_W[k * ND + d];
    g_T2[c * ND + d] = acc;
}

// ---------------- co-occurrence counts (2 blocks per batch row) ----------------
__global__ void k_cooc(const int* __restrict__ src, const int* __restrict__ dst) {
    __shared__ int ss[NL], dd[NL];
    int blk = blockIdx.x;
    int b = blk >> 1, half = blk & 1;
    int tid = threadIdx.x;
    for (int idx = tid; idx < NL; idx += 256) {
        ss[idx] = src[b * NL + idx];
        dd[idx] = dst[b * NL + idx];
    }
    __syncthreads();
    int i = half * 256 + tid;
    int qs = ss[i], qd = dd[i];
    int css = 0, csd = 0, cds = 0, cdd = 0;
    #pragma unroll 8
    for (int j = 0; j < NL; j++) {
        int s = ss[j], t = dd[j];
        css += (qs == s); csd += (qs == t);
        cds += (qd == s); cdd += (qd == t);
    }
    if (qs == 0) { css = 0; csd = 0; }
    if (qd == 0) { cds = 0; cdd = 0; }
    int ts = b * NL + i, td = TOKS + b * NL + i;
    g_cnt[ts * 2 + 0] = css; g_cnt[ts * 2 + 1] = csd;
    g_cnt[td * 2 + 0] = cds; g_cnt[td * 2 + 1] = cdd;
}

// ---------------- fused feature build + LN1 (one pass) ----------------
__global__ void k_featln(const float* __restrict__ g, const float* __restrict__ b) {
    int row = blockIdx.x, t = threadIdx.x;
    int c0 = g_cnt[row * 2], c1 = g_cnt[row * 2 + 1];
    float v = g_T2[c0 * ND + t] + g_T2[c1 * ND + t];
    g_X[(size_t)row * ND + t] = v;           // residual copy (fp32)
    __shared__ float sh[4];
    float s = v;
    for (int o = 16; o; o >>= 1) s += __shfl_xor_sync(0xffffffffu, s, o);
    int w = t >> 5;
    if ((t & 31) == 0) sh[w] = s;
    __syncthreads();
    float mu = (sh[0] + sh[1] + sh[2] + sh[3]) * (1.f / 128.f);
    __syncthreads();
    float dlt = v - mu;
    float s2 = dlt * dlt;
    for (int o = 16; o; o >>= 1) s2 += __shfl_xor_sync(0xffffffffu, s2, o);
    if ((t & 31) == 0) sh[w] = s2;
    __syncthreads();
    float var = (sh[0] + sh[1] + sh[2] + sh[3]) * (1.f / 128.f);
    float r = rsqrtf(var + 1e-5f);
    g_H[(size_t)row * ND + t] = f2tf(dlt * r * g[t] + b[t]);
}

// ============ tf32 GEMM, 3-stage cp.async (128x128 tile, occ 2) ============
#define AP 20
#define BP 136
#define NSTG 3
#define GEMM_SMEM ((NSTG * 128 * AP + NSTG * 16 * BP) * 4)
__global__ __launch_bounds__(256, 2) void gemm_tf32(
        int Aid, const float* __restrict__ Bm,
        const float* __restrict__ bias, int resid,
        int Cid, float* __restrict__ cext,
        int M, int N, int K, int act, int rndC, int kscale) {
    const float* A = buf(Aid);
    const float* res = (resid >= 0) ? buf(resid) : nullptr;
    float* C = cext ? cext : buf(Cid);
    extern __shared__ float gsm[];
    float* Asm = gsm;
    float* Bsm = gsm + NSTG * 128 * AP;
    int tid = threadIdx.x;
    int lane = tid & 31, warp = tid >> 5;
    int wm = (warp >> 1) * 32, wn = (warp & 1) * 64;
    int gid = lane >> 2, tig = lane & 3;
    int bm = blockIdx.y * 128, bn = blockIdx.x * 128;

    int a_row = tid >> 1, a_kc = (tid & 1) * 8;
    int b_row = tid >> 4, b_nc = (tid & 15) * 8;

    int nk = K / 16;
    #pragma unroll
    for (int p = 0; p < 2; p++) {
        if (p < nk) {
            int k0 = p * 16;
            const float* ga = &A[(size_t)(bm + a_row) * K + k0 + a_kc];
            cp_async16(&Asm[p * 128 * AP + a_row * AP + a_kc], ga);
            cp_async16(&Asm[p * 128 * AP + a_row * AP + a_kc + 4], ga + 4);
            const float* gb = &Bm[(size_t)(k0 + b_row) * N + bn + b_nc];
            cp_async16(&Bsm[p * 16 * BP + b_row * BP + b_nc], gb);
            cp_async16(&Bsm[p * 16 * BP + b_row * BP + b_nc + 4], gb + 4);
            asm volatile("cp.async.commit_group;");
        }
    }

    float acc[2][8][4] = {};
    for (int it = 0; it < nk; it++) {
        if (it + 1 < nk) asm volatile("cp.async.wait_group 1;");
        else             asm volatile("cp.async.wait_group 0;");
        __syncthreads();
        if (it + 2 < nk) {
            int nxt = (it + 2) % NSTG, k0 = (it + 2) * 16;
            const float* ga = &A[(size_t)(bm + a_row) * K + k0 + a_kc];
            cp_async16(&Asm[nxt * 128 * AP + a_row * AP + a_kc], ga);
            cp_async16(&Asm[nxt * 128 * AP + a_row * AP + a_kc + 4], ga + 4);
            const float* gb = &Bm[(size_t)(k0 + b_row) * N + bn + b_nc];
            cp_async16(&Bsm[nxt * 16 * BP + b_row * BP + b_nc], gb);
            cp_async16(&Bsm[nxt * 16 * BP + b_row * BP + b_nc + 4], gb + 4);
            asm volatile("cp.async.commit_group;");
        }
        const float* As = Asm + (it % NSTG) * 128 * AP;
        const float* Bs = Bsm + (it % NSTG) * 16 * BP;
        #pragma unroll
        for (int kk = 0; kk < 16; kk += 8) {
            unsigned af[2][4], bf[8][2];
            #pragma unroll
            for (int mi = 0; mi < 2; mi++) {
                int mb = wm + mi * 16 + gid;
                af[mi][0] = __float_as_uint(As[mb * AP + kk + tig]);
                af[mi][1] = __float_as_uint(As[(mb + 8) * AP + kk + tig]);
                af[mi][2] = __float_as_uint(As[mb * AP + kk + tig + 4]);
                af[mi][3] = __float_as_uint(As[(mb + 8) * AP + kk + tig + 4]);
            }
            #pragma unroll
            for (int ni = 0; ni < 8; ni++) {
                int n = wn + ni * 8 + gid;
                bf[ni][0] = __float_as_uint(Bs[(kk + tig) * BP + n]);
                bf[ni][1] = __float_as_uint(Bs[(kk + tig + 4) * BP + n]);
            }
            #pragma unroll
            for (int mi = 0; mi < 2; mi++)
                #pragma unroll
                for (int ni = 0; ni < 8; ni++)
                    mma_tf32(acc[mi][ni], af[mi], bf[ni]);
        }
    }

    #pragma unroll
    for (int mi = 0; mi < 2; mi++) {
        int r0 = bm + wm + mi * 16 + gid;
        #pragma unroll
        for (int ni = 0; ni < 8; ni++) {
            int col = bn + wn + ni * 8 + tig * 2;
            float x0 = acc[mi][ni][0], x1 = acc[mi][ni][1];
            float x2 = acc[mi][ni][2], x3 = acc[mi][ni][3];
            if (bias) {
                float bb0 = bias[col], bb1 = bias[col + 1];
                x0 += bb0; x1 += bb1; x2 += bb0; x3 += bb1;
            }
            if (kscale && col >= 128 && col < 256) {
                x0 *= 0.125f; x1 *= 0.125f; x2 *= 0.125f; x3 *= 0.125f;
            }
            if (act) {
                x0 = gelu_f(x0); x1 = gelu_f(x1);
                x2 = gelu_f(x2); x3 = gelu_f(x3);
            }
            if (rndC) {
                x0 = f2tf(x0); x1 = f2tf(x1); x2 = f2tf(x2); x3 = f2tf(x3);
            }
            if (res) {
                x0 += res[(size_t)r0 * N + col];       x1 += res[(size_t)r0 * N + col + 1];
                x2 += res[(size_t)(r0 + 8) * N + col]; x3 += res[(size_t)(r0 + 8) * N + col + 1];
            }
            *(float2*)&C[(size_t)r0 * N + col] = make_float2(x0, x1);
            *(float2*)&C[(size_t)(r0 + 8) * N + col] = make_float2(x2, x3);
        }
    }
}

// ============ WO GEMM + residual + fused LN2 (N=K=128, full rows per CTA) ============
__global__ __launch_bounds__(256, 2) void gemm_wo_ln(
        const float* __restrict__ Bm, const float* __restrict__ bias,
        const float* __restrict__ lng, const float* __restrict__ lnb) {
    const float* A = g_CTX;
    extern __shared__ float gsm[];
    float* Asm = gsm;
    float* Bsm = gsm + NSTG * 128 * AP;
    int tid = threadIdx.x;
    int lane = tid & 31, warp = tid >> 5;
    int wm = (warp >> 1) * 32, wn = (warp & 1) * 64;
    int gid = lane >> 2, tig = lane & 3;
    int bm = blockIdx.x * 128;

    int a_row = tid >> 1, a_kc = (tid & 1) * 8;
    int b_row = tid >> 4, b_nc = (tid & 15) * 8;

    const int nk = 8;  // K=128
    #pragma unroll
    for (int p = 0; p < 2; p++) {
        int k0 = p * 16;
        const float* ga = &A[(size_t)(bm + a_row) * 128 + k0 + a_kc];
        cp_async16(&Asm[p * 128 * AP + a_row * AP + a_kc], ga);
        cp_async16(&Asm[p * 128 * AP + a_row * AP + a_kc + 4], ga + 4);
        const float* gb = &Bm[(size_t)(k0 + b_row) * 128 + b_nc];
        cp_async16(&Bsm[p * 16 * BP + b_row * BP + b_nc], gb);
        cp_async16(&Bsm[p * 16 * BP + b_row * BP + b_nc + 4], gb + 4);
        asm volatile("cp.async.commit_group;");
    }

    float acc[2][8][4] = {};
    for (int it = 0; it < nk; it++) {
        if (it + 1 < nk) asm volatile("cp.async.wait_group 1;");
        else             asm volatile("cp.async.wait_group 0;");
        __syncthreads();
        if (it + 2 < nk) {
            int nxt = (it + 2) % NSTG, k0 = (it + 2) * 16;
            const float* ga = &A[(size_t)(bm + a_row) * 128 + k0 + a_kc];
            cp_async16(&Asm[nxt * 128 * AP + a_row * AP + a_kc], ga);
            cp_async16(&Asm[nxt * 128 * AP + a_row * AP + a_kc + 4], ga + 4);
            const float* gb = &Bm[(size_t)(k0 + b_row) * 128 + b_nc];
            cp_async16(&Bsm[nxt * 16 * BP + b_row * BP + b_nc], gb);
            cp_async16(&Bsm[nxt * 16 * BP + b_row * BP + b_nc + 4], gb + 4);
            asm volatile("cp.async.commit_group;");
        }
        const float* As = Asm + (it % NSTG) * 128 * AP;
        const float* Bs = Bsm + (it % NSTG) * 16 * BP;
        #pragma unroll
        for (int kk = 0; kk < 16; kk += 8) {
            unsigned af[2][4], bf[8][2];
            #pragma unroll
            for (int mi = 0; mi < 2; mi++) {
                int mb = wm + mi * 16 + gid;
                af[mi][0] = __float_as_uint(As[mb * AP + kk + tig]);
                af[mi][1] = __float_as_uint(As[(mb + 8) * AP + kk + tig]);
                af[mi][2] = __float_as_uint(As[mb * AP + kk + tig + 4]);
                af[mi][3] = __float_as_uint(As[(mb + 8) * AP + kk + tig + 4]);
            }
            #pragma unroll
            for (int ni = 0; ni < 8; ni++) {
                int n = wn + ni * 8 + gid;
                bf[ni][0] = __float_as_uint(Bs[(kk + tig) * BP + n]);
                bf[ni][1] = __float_as_uint(Bs[(kk + tig + 4) * BP + n]);
            }
            #pragma unroll
            for (int mi = 0; mi < 2; mi++)
                #pragma unroll
                for (int ni = 0; ni < 8; ni++)
                    mma_tf32(acc[mi][ni], af[mi], bf[ni]);
        }
    }

    #pragma unroll
    for (int mi = 0; mi < 2; mi++) {
        int r0 = bm + wm + mi * 16 + gid;
        #pragma unroll
        for (int ni = 0; ni < 8; ni++) {
            int col = wn + ni * 8 + tig * 2;
            float bb0 = bias[col], bb1 = bias[col + 1];
            acc[mi][ni][0] += bb0 + g_X[(size_t)r0 * ND + col];
            acc[mi][ni][1] += bb1 + g_X[(size_t)r0 * ND + col + 1];
            acc[mi][ni][2] += bb0 + g_X[(size_t)(r0 + 8) * ND + col];
            acc[mi][ni][3] += bb1 + g_X[(size_t)(r0 + 8) * ND + col + 1];
        }
    }
    __syncthreads();
    float2* ps = (float2*)gsm;
    #pragma unroll
    for (int mi = 0; mi < 2; mi++) {
        float sA = 0.f, qA = 0.f, sB = 0.f, qB = 0.f;
        #pragma unroll
        for (int ni = 0; ni < 8; ni++) {
            float x0 = acc[mi][ni][0], x1 = acc[mi][ni][1];
            float x2 = acc[mi][ni][2], x3 = acc[mi][ni][3];
            sA += x0 + x1;  qA += x0 * x0 + x1 * x1;
            sB += x2 + x3;  qB += x2 * x2 + x3 * x3;
        }
        #pragma unroll
        for (int o = 1; o <= 2; o <<= 1) {
            sA += __shfl_xor_sync(0xffffffffu, sA, o);
            qA += __shfl_xor_sync(0xffffffffu, qA, o);
            sB += __shfl_xor_sync(0xffffffffu, sB, o);
            qB += __shfl_xor_sync(0xffffffffu, qB, o);
        }
        if (tig == 0) {
            int lr = wm + mi * 16 + gid;
            ps[lr * 2 + (warp & 1)] = make_float2(sA, qA);
            ps[(lr + 8) * 2 + (warp & 1)] = make_float2(sB, qB);
        }
    }
    __syncthreads();
    #pragma unroll
    for (int mi = 0; mi < 2; mi++) {
        int lr = wm + mi * 16 + gid;
        float2 pa = ps[lr * 2], pb = ps[lr * 2 + 1];
        float mu0 = (pa.x + pb.x) * (1.f / 128.f);
        float v0  = fmaxf((pa.y + pb.y) * (1.f / 128.f) - mu0 * mu0, 0.f);
        float rv0 = rsqrtf(v0 + 1e-5f);
        float2 pc = ps[(lr + 8) * 2], pd = ps[(lr + 8) * 2 + 1];
        float mu1 = (pc.x + pd.x) * (1.f / 128.f);
        float v1  = fmaxf((pc.y + pd.y) * (1.f / 128.f) - mu1 * mu1, 0.f);
        float rv1 = rsqrtf(v1 + 1e-5f);
        int r0 = bm + lr;
        #pragma unroll
        for (int ni = 0; ni < 8; ni++) {
            int col = wn + ni * 8 + tig * 2;
            float g0 = lng[col], g1 = lng[col + 1];
            float b0 = lnb[col], b1 = lnb[col + 1];
            float x0 = acc[mi][ni][0], x1 = acc[mi][ni][1];
            float x2 = acc[mi][ni][2], x3 = acc[mi][ni][3];
            *(float2*)&g_X[(size_t)r0 * ND + col] = make_float2(x0, x1);
            *(float2*)&g_X[(size_t)(r0 + 8) * ND + col] = make_float2(x2, x3);
            *(float2*)&g_H[(size_t)r0 * ND + col] =
                make_float2(f2tf((x0 - mu0) * rv0 * g0 + b0),
                            f2tf((x1 - mu0) * rv0 * g1 + b1));
            *(float2*)&g_H[(size_t)(r0 + 8) * ND + col] =
                make_float2(f2tf((x2 - mu1) * rv1 * g0 + b0),
                            f2tf((x3 - mu1) * rv1 * g1 + b1));
        }
    }
}

// ============ fused flash attention: 64-row CTAs, 2/SM, Q in registers ============
// CTA: 128 threads = 4 warps x 16 rows. K/V single-buffered 128-key tiles;
// cross-CTA residency (2 CTAs/SM) hides the exposed loads and softmax phases.
#define FP 68
#define FQ 0
#define FK (64 * FP)
#define FV (FK + 128 * FP)
#define SM_TOT ((FV + 128 * FP) * 4)      // (64+128+128)*68*4 = 87040 B

__global__ __launch_bounds__(128, 2) void flash_tf32() {
    extern __shared__ float sm[];
    float* Qs = sm + FQ;
    float* Ks = sm + FK;
    float* Vs = sm + FV;

    int z = blockIdx.y;
    int sb = z >> 1, h = z & 1;
    const float* Qp = g_QKV + (size_t)sb * NL * 384 + h * 64;
    const float* Kp = Qp + 128;
    const float* Vp = Qp + 256;
    float* Cp = g_CTX + (size_t)sb * NL * ND + h * 64;

    int bm = blockIdx.x * 64;
    int tid = threadIdx.x, lane = tid & 31, warp = tid >> 5;
    int wm = warp * 16;
    int gid = lane >> 2, tig = lane & 3;
    int srcA = (lane & ~3) | (tig >> 1);
    int srcB = srcA | 2;
    bool odd = tig & 1;

    // prologue: Q (64 rows) + K0/V0 (128 rows each)
    {
        int qr = tid >> 1, qc = (tid & 1) * 32;
        #pragma unroll
        for (int i = 0; i < 8; i++)
            cp_async16(&Qs[qr * FP + qc + i * 4],
                       &Qp[(size_t)(bm + qr) * 384 + qc + i * 4]);
        #pragma unroll
        for (int i = 0; i < 16; i++)
            cp_async16(&Ks[tid * FP + i * 4], &Kp[(size_t)tid * 384 + i * 4]);
        #pragma unroll
        for (int i = 0; i < 16; i++)
            cp_async16(&Vs[tid * FP + i * 4], &Vp[(size_t)tid * 384 + i * 4]);
        asm volatile("cp.async.commit_group;");
    }

    unsigned aq[8][4];                    // Q fragments, loaded once
    float co[8][4] = {};
    float m_r[2] = {-1e30f, -1e30f};
    float l_r[2] = {0.f, 0.f};

    for (int j = 0; j < 4; j++) {
        asm volatile("cp.async.wait_group 0;");
        __syncthreads();
        if (j == 0) {
            int mb = wm + gid;
            #pragma unroll
            for (int kc = 0; kc < 8; kc++) {
                int kk = kc * 8;
                aq[kc][0] = __float_as_uint(Qs[mb * FP + kk + tig]);
                aq[kc][1] = __float_as_uint(Qs[(mb + 8) * FP + kk + tig]);
                aq[kc][2] = __float_as_uint(Qs[mb * FP + kk + tig + 4]);
                aq[kc][3] = __float_as_uint(Qs[(mb + 8) * FP + kk + tig + 4]);
            }
        }

        // ---- S = Q @ K'^T (warp tile 16 x 128) ----
        float cs[16][4] = {};
        #pragma unroll
        for (int kc = 0; kc < 8; kc++) {
            int kk = kc * 8;
            #pragma unroll
            for (int ni = 0; ni < 16; ni++) {
                unsigned bf[2];
                int n = ni * 8 + gid;
                bf[0] = __float_as_uint(Ks[n * FP + kk + tig]);
                bf[1] = __float_as_uint(Ks[n * FP + kk + tig + 4]);
                mma_tf32(cs[ni], aq[kc], bf);
            }
        }

        // ---- online softmax (rows fully inside warp) ----
        float tm0 = -1e30f, tm1 = -1e30f;
        #pragma unroll
        for (int ni = 0; ni < 16; ni++) {
            tm0 = fmaxf(tm0, fmaxf(cs[ni][0], cs[ni][1]));
            tm1 = fmaxf(tm1, fmaxf(cs[ni][2], cs[ni][3]));
        }
        tm0 = fmaxf(tm0, __shfl_xor_sync(0xffffffffu, tm0, 1));
        tm0 = fmaxf(tm0, __shfl_xor_sync(0xffffffffu, tm0, 2));
        tm1 = fmaxf(tm1, __shfl_xor_sync(0xffffffffu, tm1, 1));
        tm1 = fmaxf(tm1, __shfl_xor_sync(0xffffffffu, tm1, 2));
        float nm0 = fmaxf(m_r[0], tm0);
        float nm1 = fmaxf(m_r[1], tm1);
        float a0 = __expf(m_r[0] - nm0);
        float a1 = __expf(m_r[1] - nm1);
        float ts0 = 0.f, ts1 = 0.f;
        #pragma unroll
        for (int ni = 0; ni < 16; ni++) {
            cs[ni][0] = __expf(cs[ni][0] - nm0);
            cs[ni][1] = __expf(cs[ni][1] - nm0);
            cs[ni][2] = __expf(cs[ni][2] - nm1);
            cs[ni][3] = __expf(cs[ni][3] - nm1);
            ts0 += cs[ni][0] + cs[ni][1];
            ts1 += cs[ni][2] + cs[ni][3];
        }
        ts0 += __shfl_xor_sync(0xffffffffu, ts0, 1);
        ts0 += __shfl_xor_sync(0xffffffffu, ts0, 2);
        ts1 += __shfl_xor_sync(0xffffffffu, ts1, 1);
        ts1 += __shfl_xor_sync(0xffffffffu, ts1, 2);
        l_r[0] = l_r[0] * a0 + ts0;
        l_r[1] = l_r[1] * a1 + ts1;
        m_r[0] = nm0;
        m_r[1] = nm1;
        #pragma unroll
        for (int ni = 0; ni < 8; ni++) {
            co[ni][0] *= a0; co[ni][1] *= a0;
            co[ni][2] *= a1; co[ni][3] *= a1;
        }

        // ---- O += P @ V: A-frags via 4-lane shfl permute ----
        #pragma unroll
        for (int kc = 0; kc < 16; kc++) {
            float v00 = __shfl_sync(0xffffffffu, cs[kc][0], srcA);
            float v01 = __shfl_sync(0xffffffffu, cs[kc][1], srcA);
            float v10 = __shfl_sync(0xffffffffu, cs[kc][2], srcA);
            float v11 = __shfl_sync(0xffffffffu, cs[kc][3], srcA);
            float v20 = __shfl_sync(0xffffffffu, cs[kc][0], srcB);
            float v21 = __shfl_sync(0xffffffffu, cs[kc][1], srcB);
            float v30 = __shfl_sync(0xffffffffu, cs[kc][2], srcB);
            float v31 = __shfl_sync(0xffffffffu, cs[kc][3], srcB);
            unsigned af[4];
            af[0] = __float_as_uint(f2tf(odd ? v01 : v00));
            af[1] = __float_as_uint(f2tf(odd ? v11 : v10));
            af[2] = __float_as_uint(f2tf(odd ? v21 : v20));
            af[3] = __float_as_uint(f2tf(odd ? v31 : v30));
            int kk = kc * 8;
            #pragma unroll
            for (int ni = 0; ni < 8; ni++) {
                unsigned bf[2];
                int n = ni * 8 + gid;
                bf[0] = __float_as_uint(Vs[(kk + tig) * FP + n]);
                bf[1] = __float_as_uint(Vs[(kk + tig + 4) * FP + n]);
                mma_tf32(co[ni], af, bf);
            }
        }

        // single-buffered K/V: all reads done before next loads overwrite
        if (j + 1 < 4) {
            __syncthreads();
            int grow = (j + 1) * 128 + tid;
            #pragma unroll
            for (int i = 0; i < 16; i++)
                cp_async16(&Ks[tid * FP + i * 4], &Kp[(size_t)grow * 384 + i * 4]);
            #pragma unroll
            for (int i = 0; i < 16; i++)
                cp_async16(&Vs[tid * FP + i * 4], &Vp[(size_t)grow * 384 + i * 4]);
            asm volatile("cp.async.commit_group;");
        }
    }

    // ---- normalize and store (pre-rounded: A-side of WO GEMM) ----
    {
        float inv0 = 1.f / l_r[0];
        float inv1 = 1.f / l_r[1];
        int r0 = bm + wm + gid;
        #pragma unroll
        for (int ni = 0; ni < 8; ni++) {
            int col = ni * 8 + tig * 2;
            *(float2*)&Cp[(size_t)r0 * ND + col] =
                make_float2(f2tf(co[ni][0] * inv0), f2tf(co[ni][1] * inv0));
            *(float2*)&Cp[(size_t)(r0 + 8) * ND + col] =
                make_float2(f2tf(co[ni][2] * inv1), f2tf(co[ni][3] * inv1));
        }
    }
}

// ---------------- launch ----------------
extern "C" void kernel_launch(void* const* d_in, const int* in_sizes, int n_in,
                              void* d_out, int out_size) {
    const int*   src    = (const int*)d_in[0];
    const int*   dst    = (const int*)d_in[1];
    const float* w1     = (const float*)d_in[2];
    const float* b1     = (const float*)d_in[3];
    const float* w2     = (const float*)d_in[4];
    const float* b2     = (const float*)d_in[5];
    const float* proj_w = (const float*)d_in[6];
    const float* proj_b = (const float*)d_in[7];
    const float* ln1_g  = (const float*)d_in[8];
    const float* ln1_b  = (const float*)d_in[9];
    const float* w_qkv  = (const float*)d_in[10];
    const float* b_qkv  = (const float*)d_in[11];
    const float* w_o    = (const float*)d_in[12];
    const float* b_o    = (const float*)d_in[13];
    const float* ln2_g  = (const float*)d_in[14];
    const float* ln2_b  = (const float*)d_in[15];
    const float* w_ff1  = (const float*)d_in[16];
    const float* b_ff1  = (const float*)d_in[17];
    const float* w_ff2  = (const float*)d_in[18];
    const float* b_ff2  = (const float*)d_in[19];
    float* out = (float*)d_out;

    cudaFuncSetAttribute(flash_tf32, cudaFuncAttributeMaxDynamicSharedMemorySize, SM_TOT);
    cudaFuncSetAttribute(gemm_tf32, cudaFuncAttributeMaxDynamicSharedMemorySize, GEMM_SMEM);
    cudaFuncSetAttribute(gemm_wo_ln, cudaFuncAttributeMaxDynamicSharedMemorySize, GEMM_SMEM);

    float* WR;
    {
        void* p; cudaGetSymbolAddress(&p, g_WR); WR = (float*)p;
    }

    // launches 1-5 (precompute), then GEMMs start at launch #6 for ncu -s 5
    k_rnd_all<<<196608 / 256, 256>>>(w_qkv, w_o, w_ff1, w_ff2);
    k_Wb<<<ND + 1, ND>>>(w2, proj_w, b2, proj_b);
    k_table<<<513, ND>>>(w1, b1);
    k_cooc<<<2 * NB, 256>>>(src, dst);
    k_featln<<<NTOK, ND>>>(ln1_g, ln1_b);

    // transformer (both streams batched: 65536 tokens)
    gemm_tf32<<<dim3(3, NTOK / 128), 256, GEMM_SMEM>>>(BUF_H, WR + WR_QKV, b_qkv, -1,
        BUF_QKV, nullptr, NTOK, 384, 128, 0, 1, 1);
    flash_tf32<<<dim3(NL / 64, NHB), 128, SM_TOT>>>();
    gemm_wo_ln<<<NTOK / 128, 256, GEMM_SMEM>>>(WR + WR_WO, b_o, ln2_g, ln2_b);
    gemm_tf32<<<dim3(4, NTOK / 128), 256, GEMM_SMEM>>>(BUF_H, WR + WR_FF1, b_ff1, -1,
        BUF_FF, nullptr, NTOK, 512, 128, 1, 1, 0);
    gemm_tf32<<<dim3(1, NTOK / 128), 256, GEMM_SMEM>>>(BUF_FF, WR + WR_FF2, b_ff2, BUF_X,
        BUF_X, out, NTOK, 128, 512, 0, 0, 0);
}

// round 14
// speedup vs baseline: 1.0759x; 1.0759x over previous
#include <cuda_runtime.h>
#include <math.h>

#define NB    64
#define NL    512
#define ND    128
#define TOKS  32768          // B*L per stream
#define NTOK  65536          // 2*B*L
#define NHB   256            // 2*B*H attention batches

// ---------------- scratch (device globals; no allocation allowed) ----------------
__device__ int   g_cnt[NTOK * 2];
__device__ float g_W[ND * ND];
__device__ float g_biasT[ND];
__device__ float g_T2[513 * ND];
__device__ float g_X[(size_t)NTOK * ND];
__device__ float g_H[(size_t)NTOK * ND];
__device__ float g_QKV[(size_t)NTOK * 3 * ND];
__device__ float g_CTX[(size_t)NTOK * ND];
__device__ float g_FF[(size_t)NTOK * 4 * ND];
__device__ float g_WR[196608];   // pre-rounded weights: QKV | WO | FF1 | FF2

#define WR_QKV 0
#define WR_WO  49152
#define WR_FF1 65536
#define WR_FF2 131072

#define BUF_X    0
#define BUF_H    1
#define BUF_QKV  2
#define BUF_CTX  3
#define BUF_FF   4
__device__ __forceinline__ float* buf(int id) {
    switch (id) {
        case BUF_X:   return g_X;
        case BUF_H:   return g_H;
        case BUF_QKV: return g_QKV;
        case BUF_CTX: return g_CTX;
        default:      return g_FF;
    }
}

// fp32 -> tf32 (round to nearest)
__device__ __forceinline__ float f2tf(float x) {
    unsigned r;
    asm("cvt.rna.tf32.f32 %0, %1;" : "=r"(r) : "f"(x));
    return __uint_as_float(r);
}

__device__ __forceinline__ void mma_tf32(float* c, const unsigned* a, const unsigned* b) {
    asm volatile(
        "mma.sync.aligned.m16n8k8.row.col.f32.tf32.tf32.f32 "
        "{%0,%1,%2,%3}, {%4,%5,%6,%7}, {%8,%9}, {%0,%1,%2,%3};"
        : "+f"(c[0]), "+f"(c[1]), "+f"(c[2]), "+f"(c[3])
        : "r"(a[0]), "r"(a[1]), "r"(a[2]), "r"(a[3]), "r"(b[0]), "r"(b[1]));
}

__device__ __forceinline__ void cp_async16(float* smem_dst, const float* gsrc) {
    unsigned saddr = (unsigned)__cvta_generic_to_shared(smem_dst);
    asm volatile("cp.async.cg.shared.global [%0], [%1], 16;" :: "r"(saddr), "l"(gsrc));
}

// fast exact-gelu: Abramowitz-Stegun 7.1.26 erf (abs err 1.5e-7)
__device__ __forceinline__ float gelu_f(float x) {
    float z  = x * 0.70710678118654752f;
    float az = fabsf(z);
    float t  = __fdividef(1.f, fmaf(0.3275911f, az, 1.f));
    float p  = t * (0.254829592f + t * (-0.284496736f + t * (1.421413741f +
               t * (-1.453152027f + t * 1.061405429f))));
    float er = copysignf(1.f - p * __expf(-z * z), z);
    return 0.5f * x * (1.f + er);
}

// ---------------- precompute: round all 4 weight matrices in ONE launch ----------------
__global__ void k_rnd_all(const float* __restrict__ qkv, const float* __restrict__ wo,
                          const float* __restrict__ ff1, const float* __restrict__ ff2) {
    int i = blockIdx.x * 256 + threadIdx.x;      // 196608 total
    const float* s; int off;
    if (i < 49152)        { s = qkv; off = i; }
    else if (i < 65536)   { s = wo;  off = i - 49152; }
    else if (i < 131072)  { s = ff1; off = i - 65536; }
    else                  { s = ff2; off = i - 131072; }
    g_WR[i] = f2tf(s[off]);
}

// W = w2 @ proj_w (blocks 0..127) and biasT (block 128) in one launch
__global__ void k_Wb(const float* __restrict__ w2, const float* __restrict__ proj_w,
                     const float* __restrict__ b2, const float* __restrict__ proj_b) {
    int d = threadIdx.x;
    if (blockIdx.x < ND) {
        int k = blockIdx.x;
        float acc = 0.f;
        #pragma unroll 8
        for (int j = 0; j < ND; j++) acc += w2[k * ND + j] * proj_w[j * ND + d];
        g_W[k * ND + d] = acc;
    } else {
        float acc = proj_b[d];
        #pragma unroll 8
        for (int k = 0; k < ND; k++) acc += 2.f * b2[k] * proj_w[k * ND + d];
        g_biasT[d] = acc;
    }
}

__global__ void k_table(const float* __restrict__ w1, const float* __restrict__ b1) {
    __shared__ float h[ND];
    int c = blockIdx.x, d = threadIdx.x;
    h[d] = fmaxf((float)c * w1[d] + b1[d], 0.f);
    __syncthreads();
    float acc = 0.5f * g_biasT[d];
    #pragma unroll 8
    for (int k = 0; k < ND; k++) acc += h[k] * g_W[k * ND + d];
    g_T2[c * ND + d] = acc;
}

// ---------------- co-occurrence counts (2 blocks per batch row) ----------------
__global__ void k_cooc(const int* __restrict__ src, const int* __restrict__ dst) {
    __shared__ int ss[NL], dd[NL];
    int blk = blockIdx.x;
    int b = blk >> 1, half = blk & 1;
    int tid = threadIdx.x;
    for (int idx = tid; idx < NL; idx += 256) {
        ss[idx] = src[b * NL + idx];
        dd[idx] = dst[b * NL + idx];
    }
    __syncthreads();
    int i = half * 256 + tid;
    int qs = ss[i], qd = dd[i];
    int css = 0, csd = 0, cds = 0, cdd = 0;
    #pragma unroll 8
    for (int j = 0; j < NL; j++) {
        int s = ss[j], t = dd[j];
        css += (qs == s); csd += (qs == t);
        cds += (qd == s); cdd += (qd == t);
    }
    if (qs == 0) { css = 0; csd = 0; }
    if (qd == 0) { cds = 0; cdd = 0; }
    int ts = b * NL + i, td = TOKS + b * NL + i;
    g_cnt[ts * 2 + 0] = css; g_cnt[ts * 2 + 1] = csd;
    g_cnt[td * 2 + 0] = cds; g_cnt[td * 2 + 1] = cdd;
}

// ---------------- fused feature build + LN1 (one pass) ----------------
__global__ void k_featln(const float* __restrict__ g, const float* __restrict__ b) {
    int row = blockIdx.x, t = threadIdx.x;
    int c0 = g_cnt[row * 2], c1 = g_cnt[row * 2 + 1];
    float v = g_T2[c0 * ND + t] + g_T2[c1 * ND + t];
    g_X[(size_t)row * ND + t] = v;           // residual copy (fp32)
    __shared__ float sh[4];
    float s = v;
    for (int o = 16; o; o >>= 1) s += __shfl_xor_sync(0xffffffffu, s, o);
    int w = t >> 5;
    if ((t & 31) == 0) sh[w] = s;
    __syncthreads();
    float mu = (sh[0] + sh[1] + sh[2] + sh[3]) * (1.f / 128.f);
    __syncthreads();
    float dlt = v - mu;
    float s2 = dlt * dlt;
    for (int o = 16; o; o >>= 1) s2 += __shfl_xor_sync(0xffffffffu, s2, o);
    if ((t & 31) == 0) sh[w] = s2;
    __syncthreads();
    float var = (sh[0] + sh[1] + sh[2] + sh[3]) * (1.f / 128.f);
    float r = rsqrtf(var + 1e-5f);
    g_H[(size_t)row * ND + t] = f2tf(dlt * r * g[t] + b[t]);
}

// ============ tf32 GEMM, 3-stage cp.async (128x128 tile, occ 2) ============
#define AP 20
#define BP 136
#define NSTG 3
#define GEMM_SMEM ((NSTG * 128 * AP + NSTG * 16 * BP) * 4)
__global__ __launch_bounds__(256, 2) void gemm_tf32(
        int Aid, const float* __restrict__ Bm,
        const float* __restrict__ bias, int resid,
        int Cid, float* __restrict__ cext,
        int M, int N, int K, int act, int rndC, int kscale) {
    const float* A = buf(Aid);
    const float* res = (resid >= 0) ? buf(resid) : nullptr;
    float* C = cext ? cext : buf(Cid);
    extern __shared__ float gsm[];
    float* Asm = gsm;
    float* Bsm = gsm + NSTG * 128 * AP;
    int tid = threadIdx.x;
    int lane = tid & 31, warp = tid >> 5;
    int wm = (warp >> 1) * 32, wn = (warp & 1) * 64;
    int gid = lane >> 2, tig = lane & 3;
    int bm = blockIdx.y * 128, bn = blockIdx.x * 128;

    int a_row = tid >> 1, a_kc = (tid & 1) * 8;
    int b_row = tid >> 4, b_nc = (tid & 15) * 8;

    int nk = K / 16;
    #pragma unroll
    for (int p = 0; p < 2; p++) {
        if (p < nk) {
            int k0 = p * 16;
            const float* ga = &A[(size_t)(bm + a_row) * K + k0 + a_kc];
            cp_async16(&Asm[p * 128 * AP + a_row * AP + a_kc], ga);
            cp_async16(&Asm[p * 128 * AP + a_row * AP + a_kc + 4], ga + 4);
            const float* gb = &Bm[(size_t)(k0 + b_row) * N + bn + b_nc];
            cp_async16(&Bsm[p * 16 * BP + b_row * BP + b_nc], gb);
            cp_async16(&Bsm[p * 16 * BP + b_row * BP + b_nc + 4], gb + 4);
            asm volatile("cp.async.commit_group;");
        }
    }

    float acc[2][8][4] = {};
    for (int it = 0; it < nk; it++) {
        if (it + 1 < nk) asm volatile("cp.async.wait_group 1;");
        else             asm volatile("cp.async.wait_group 0;");
        __syncthreads();
        if (it + 2 < nk) {
            int nxt = (it + 2) % NSTG, k0 = (it + 2) * 16;
            const float* ga = &A[(size_t)(bm + a_row) * K + k0 + a_kc];
            cp_async16(&Asm[nxt * 128 * AP + a_row * AP + a_kc], ga);
            cp_async16(&Asm[nxt * 128 * AP + a_row * AP + a_kc + 4], ga + 4);
            const float* gb = &Bm[(size_t)(k0 + b_row) * N + bn + b_nc];
            cp_async16(&Bsm[nxt * 16 * BP + b_row * BP + b_nc], gb);
            cp_async16(&Bsm[nxt * 16 * BP + b_row * BP + b_nc + 4], gb + 4);
            asm volatile("cp.async.commit_group;");
        }
        const float* As = Asm + (it % NSTG) * 128 * AP;
        const float* Bs = Bsm + (it % NSTG) * 16 * BP;
        #pragma unroll
        for (int kk = 0; kk < 16; kk += 8) {
            unsigned af[2][4], bf[8][2];
            #pragma unroll
            for (int mi = 0; mi < 2; mi++) {
                int mb = wm + mi * 16 + gid;
                af[mi][0] = __float_as_uint(As[mb * AP + kk + tig]);
                af[mi][1] = __float_as_uint(As[(mb + 8) * AP + kk + tig]);
                af[mi][2] = __float_as_uint(As[mb * AP + kk + tig + 4]);
                af[mi][3] = __float_as_uint(As[(mb + 8) * AP + kk + tig + 4]);
            }
            #pragma unroll
            for (int ni = 0; ni < 8; ni++) {
                int n = wn + ni * 8 + gid;
                bf[ni][0] = __float_as_uint(Bs[(kk + tig) * BP + n]);
                bf[ni][1] = __float_as_uint(Bs[(kk + tig + 4) * BP + n]);
            }
            #pragma unroll
            for (int mi = 0; mi < 2; mi++)
                #pragma unroll
                for (int ni = 0; ni < 8; ni++)
                    mma_tf32(acc[mi][ni], af[mi], bf[ni]);
        }
    }

    #pragma unroll
    for (int mi = 0; mi < 2; mi++) {
        int r0 = bm + wm + mi * 16 + gid;
        #pragma unroll
        for (int ni = 0; ni < 8; ni++) {
            int col = bn + wn + ni * 8 + tig * 2;
            float x0 = acc[mi][ni][0], x1 = acc[mi][ni][1];
            float x2 = acc[mi][ni][2], x3 = acc[mi][ni][3];
            if (bias) {
                float bb0 = bias[col], bb1 = bias[col + 1];
                x0 += bb0; x1 += bb1; x2 += bb0; x3 += bb1;
            }
            if (kscale && col >= 128 && col < 256) {
                x0 *= 0.125f; x1 *= 0.125f; x2 *= 0.125f; x3 *= 0.125f;
            }
            if (act) {
                x0 = gelu_f(x0); x1 = gelu_f(x1);
                x2 = gelu_f(x2); x3 = gelu_f(x3);
            }
            if (rndC) {
                x0 = f2tf(x0); x1 = f2tf(x1); x2 = f2tf(x2); x3 = f2tf(x3);
            }
            if (res) {
                x0 += res[(size_t)r0 * N + col];       x1 += res[(size_t)r0 * N + col + 1];
                x2 += res[(size_t)(r0 + 8) * N + col]; x3 += res[(size_t)(r0 + 8) * N + col + 1];
            }
            *(float2*)&C[(size_t)r0 * N + col] = make_float2(x0, x1);
            *(float2*)&C[(size_t)(r0 + 8) * N + col] = make_float2(x2, x3);
        }
    }
}

// ============ WO GEMM + residual + fused LN2 (N=K=128, full rows per CTA) ============
__global__ __launch_bounds__(256, 2) void gemm_wo_ln(
        const float* __restrict__ Bm, const float* __restrict__ bias,
        const float* __restrict__ lng, const float* __restrict__ lnb) {
    const float* A = g_CTX;
    extern __shared__ float gsm[];
    float* Asm = gsm;
    float* Bsm = gsm + NSTG * 128 * AP;
    int tid = threadIdx.x;
    int lane = tid & 31, warp = tid >> 5;
    int wm = (warp >> 1) * 32, wn = (warp & 1) * 64;
    int gid = lane >> 2, tig = lane & 3;
    int bm = blockIdx.x * 128;

    int a_row = tid >> 1, a_kc = (tid & 1) * 8;
    int b_row = tid >> 4, b_nc = (tid & 15) * 8;

    const int nk = 8;  // K=128
    #pragma unroll
    for (int p = 0; p < 2; p++) {
        int k0 = p * 16;
        const float* ga = &A[(size_t)(bm + a_row) * 128 + k0 + a_kc];
        cp_async16(&Asm[p * 128 * AP + a_row * AP + a_kc], ga);
        cp_async16(&Asm[p * 128 * AP + a_row * AP + a_kc + 4], ga + 4);
        const float* gb = &Bm[(size_t)(k0 + b_row) * 128 + b_nc];
        cp_async16(&Bsm[p * 16 * BP + b_row * BP + b_nc], gb);
        cp_async16(&Bsm[p * 16 * BP + b_row * BP + b_nc + 4], gb + 4);
        asm volatile("cp.async.commit_group;");
    }

    float acc[2][8][4] = {};
    for (int it = 0; it < nk; it++) {
        if (it + 1 < nk) asm volatile("cp.async.wait_group 1;");
        else             asm volatile("cp.async.wait_group 0;");
        __syncthreads();
        if (it + 2 < nk) {
            int nxt = (it + 2) % NSTG, k0 = (it + 2) * 16;
            const float* ga = &A[(size_t)(bm + a_row) * 128 + k0 + a_kc];
            cp_async16(&Asm[nxt * 128 * AP + a_row * AP + a_kc], ga);
            cp_async16(&Asm[nxt * 128 * AP + a_row * AP + a_kc + 4], ga + 4);
            const float* gb = &Bm[(size_t)(k0 + b_row) * 128 + b_nc];
            cp_async16(&Bsm[nxt * 16 * BP + b_row * BP + b_nc], gb);
            cp_async16(&Bsm[nxt * 16 * BP + b_row * BP + b_nc + 4], gb + 4);
            asm volatile("cp.async.commit_group;");
        }
        const float* As = Asm + (it % NSTG) * 128 * AP;
        const float* Bs = Bsm + (it % NSTG) * 16 * BP;
        #pragma unroll
        for (int kk = 0; kk < 16; kk += 8) {
            unsigned af[2][4], bf[8][2];
            #pragma unroll
            for (int mi = 0; mi < 2; mi++) {
                int mb = wm + mi * 16 + gid;
                af[mi][0] = __float_as_uint(As[mb * AP + kk + tig]);
                af[mi][1] = __float_as_uint(As[(mb + 8) * AP + kk + tig]);
                af[mi][2] = __float_as_uint(As[mb * AP + kk + tig + 4]);
                af[mi][3] = __float_as_uint(As[(mb + 8) * AP + kk + tig + 4]);
            }
            #pragma unroll
            for (int ni = 0; ni < 8; ni++) {
                int n = wn + ni * 8 + gid;
                bf[ni][0] = __float_as_uint(Bs[(kk + tig) * BP + n]);
                bf[ni][1] = __float_as_uint(Bs[(kk + tig + 4) * BP + n]);
            }
            #pragma unroll
            for (int mi = 0; mi < 2; mi++)
                #pragma unroll
                for (int ni = 0; ni < 8; ni++)
                    mma_tf32(acc[mi][ni], af[mi], bf[ni]);
        }
    }

    #pragma unroll
    for (int mi = 0; mi < 2; mi++) {
        int r0 = bm + wm + mi * 16 + gid;
        #pragma unroll
        for (int ni = 0; ni < 8; ni++) {
            int col = wn + ni * 8 + tig * 2;
            float bb0 = bias[col], bb1 = bias[col + 1];
            acc[mi][ni][0] += bb0 + g_X[(size_t)r0 * ND + col];
            acc[mi][ni][1] += bb1 + g_X[(size_t)r0 * ND + col + 1];
            acc[mi][ni][2] += bb0 + g_X[(size_t)(r0 + 8) * ND + col];
            acc[mi][ni][3] += bb1 + g_X[(size_t)(r0 + 8) * ND + col + 1];
        }
    }
    __syncthreads();
    float2* ps = (float2*)gsm;
    #pragma unroll
    for (int mi = 0; mi < 2; mi++) {
        float sA = 0.f, qA = 0.f, sB = 0.f, qB = 0.f;
        #pragma unroll
        for (int ni = 0; ni < 8; ni++) {
            float x0 = acc[mi][ni][0], x1 = acc[mi][ni][1];
            float x2 = acc[mi][ni][2], x3 = acc[mi][ni][3];
            sA += x0 + x1;  qA += x0 * x0 + x1 * x1;
            sB += x2 + x3;  qB += x2 * x2 + x3 * x3;
        }
        #pragma unroll
        for (int o = 1; o <= 2; o <<= 1) {
            sA += __shfl_xor_sync(0xffffffffu, sA, o);
            qA += __shfl_xor_sync(0xffffffffu, qA, o);
            sB += __shfl_xor_sync(0xffffffffu, sB, o);
            qB += __shfl_xor_sync(0xffffffffu, qB, o);
        }
        if (tig == 0) {
            int lr = wm + mi * 16 + gid;
            ps[lr * 2 + (warp & 1)] = make_float2(sA, qA);
            ps[(lr + 8) * 2 + (warp & 1)] = make_float2(sB, qB);
        }
    }
    __syncthreads();
    #pragma unroll
    for (int mi = 0; mi < 2; mi++) {
        int lr = wm + mi * 16 + gid;
        float2 pa = ps[lr * 2], pb = ps[lr * 2 + 1];
        float mu0 = (pa.x + pb.x) * (1.f / 128.f);
        float v0  = fmaxf((pa.y + pb.y) * (1.f / 128.f) - mu0 * mu0, 0.f);
        float rv0 = rsqrtf(v0 + 1e-5f);
        float2 pc = ps[(lr + 8) * 2], pd = ps[(lr + 8) * 2 + 1];
        float mu1 = (pc.x + pd.x) * (1.f / 128.f);
        float v1  = fmaxf((pc.y + pd.y) * (1.f / 128.f) - mu1 * mu1, 0.f);
        float rv1 = rsqrtf(v1 + 1e-5f);
        int r0 = bm + lr;
        #pragma unroll
        for (int ni = 0; ni < 8; ni++) {
            int col = wn + ni * 8 + tig * 2;
            float g0 = lng[col], g1 = lng[col + 1];
            float b0 = lnb[col], b1 = lnb[col + 1];
            float x0 = acc[mi][ni][0], x1 = acc[mi][ni][1];
            float x2 = acc[mi][ni][2], x3 = acc[mi][ni][3];
            *(float2*)&g_X[(size_t)r0 * ND + col] = make_float2(x0, x1);
            *(float2*)&g_X[(size_t)(r0 + 8) * ND + col] = make_float2(x2, x3);
            *(float2*)&g_H[(size_t)r0 * ND + col] =
                make_float2(f2tf((x0 - mu0) * rv0 * g0 + b0),
                            f2tf((x1 - mu0) * rv0 * g1 + b1));
            *(float2*)&g_H[(size_t)(r0 + 8) * ND + col] =
                make_float2(f2tf((x2 - mu1) * rv1 * g0 + b0),
                            f2tf((x3 - mu1) * rv1 * g1 + b1));
        }
    }
}

// ============ fused flash attention (R12 config + Q-in-registers) ============
// CTA: 256 threads = 8 warps x 16 rows, 128-row Q block, K/V double-buffered.
#define FP 68
#define FQ 0
#define FK (128 * FP)
#define FV (FK + 2 * 128 * FP)
#define SM_TOT ((FV + 2 * 128 * FP) * 4)

__global__ __launch_bounds__(256, 1) void flash_tf32() {
    extern __shared__ float sm[];
    float* Qs = sm + FQ;
    float* Ks = sm + FK;   // [2][128*FP]
    float* Vs = sm + FV;   // [2][128*FP]

    int z = blockIdx.y;
    int sb = z >> 1, h = z & 1;
    const float* Qp = g_QKV + (size_t)sb * NL * 384 + h * 64;
    const float* Kp = Qp + 128;
    const float* Vp = Qp + 256;
    float* Cp = g_CTX + (size_t)sb * NL * ND + h * 64;

    int bm = blockIdx.x * 128;
    int tid = threadIdx.x, lane = tid & 31, warp = tid >> 5;
    int wm = warp * 16;
    int gid = lane >> 2, tig = lane & 3;
    int srcA = (lane & ~3) | (tig >> 1);
    int srcB = srcA | 2;
    bool odd = tig & 1;

    int lrow = tid >> 1, lcol = (tid & 1) * 32;

    #pragma unroll
    for (int i = 0; i < 8; i++)
        cp_async16(&Qs[lrow * FP + lcol + i * 4],
                   &Qp[(size_t)(bm + lrow) * 384 + lcol + i * 4]);
    #pragma unroll
    for (int i = 0; i < 8; i++)
        cp_async16(&Ks[lrow * FP + lcol + i * 4],
                   &Kp[(size_t)lrow * 384 + lcol + i * 4]);
    #pragma unroll
    for (int i = 0; i < 8; i++)
        cp_async16(&Vs[lrow * FP + lcol + i * 4],
                   &Vp[(size_t)lrow * 384 + lcol + i * 4]);
    asm volatile("cp.async.commit_group;");

    unsigned aq[8][4];                    // Q fragments, loaded once at j=0
    float co[8][4] = {};
    float m_r[2] = {-1e30f, -1e30f};
    float l_r[2] = {0.f, 0.f};

    for (int j = 0; j < 4; j++) {
        asm volatile("cp.async.wait_group 0;");
        __syncthreads();
        if (j == 0) {
            int mb = wm + gid;
            #pragma unroll
            for (int kc = 0; kc < 8; kc++) {
                int kk = kc * 8;
                aq[kc][0] = __float_as_uint(Qs[mb * FP + kk + tig]);
                aq[kc][1] = __float_as_uint(Qs[(mb + 8) * FP + kk + tig]);
                aq[kc][2] = __float_as_uint(Qs[mb * FP + kk + tig + 4]);
                aq[kc][3] = __float_as_uint(Qs[(mb + 8) * FP + kk + tig + 4]);
            }
        }
        if (j + 1 < 4) {
            int nb = (j + 1) & 1;
            int grow = (j + 1) * 128 + lrow;
            #pragma unroll
            for (int i = 0; i < 8; i++)
                cp_async16(&Ks[nb * 128 * FP + lrow * FP + lcol + i * 4],
                           &Kp[(size_t)grow * 384 + lcol + i * 4]);
            #pragma unroll
            for (int i = 0; i < 8; i++)
                cp_async16(&Vs[nb * 128 * FP + lrow * FP + lcol + i * 4],
                           &Vp[(size_t)grow * 384 + lcol + i * 4]);
            asm volatile("cp.async.commit_group;");
        }
        const float* Kc = Ks + (j & 1) * 128 * FP;
        const float* Vc = Vs + (j & 1) * 128 * FP;

        // ---- S = Q @ K'^T (warp tile 16 x 128) ----
        float cs[16][4] = {};
        #pragma unroll
        for (int kc = 0; kc < 8; kc++) {
            int kk = kc * 8;
            #pragma unroll
            for (int ni = 0; ni < 16; ni++) {
                unsigned bf[2];
                int n = ni * 8 + gid;
                bf[0] = __float_as_uint(Kc[n * FP + kk + tig]);
                bf[1] = __float_as_uint(Kc[n * FP + kk + tig + 4]);
                mma_tf32(cs[ni], aq[kc], bf);
            }
        }

        // ---- online softmax (rows fully inside warp) ----
        float tm0 = -1e30f, tm1 = -1e30f;
        #pragma unroll
        for (int ni = 0; ni < 16; ni++) {
            tm0 = fmaxf(tm0, fmaxf(cs[ni][0], cs[ni][1]));
            tm1 = fmaxf(tm1, fmaxf(cs[ni][2], cs[ni][3]));
        }
        tm0 = fmaxf(tm0, __shfl_xor_sync(0xffffffffu, tm0, 1));
        tm0 = fmaxf(tm0, __shfl_xor_sync(0xffffffffu, tm0, 2));
        tm1 = fmaxf(tm1, __shfl_xor_sync(0xffffffffu, tm1, 1));
        tm1 = fmaxf(tm1, __shfl_xor_sync(0xffffffffu, tm1, 2));
        float nm0 = fmaxf(m_r[0], tm0);
        float nm1 = fmaxf(m_r[1], tm1);
        float a0 = __expf(m_r[0] - nm0);
        float a1 = __expf(m_r[1] - nm1);
        float ts0 = 0.f, ts1 = 0.f;
        #pragma unroll
        for (int ni = 0; ni < 16; ni++) {
            cs[ni][0] = __expf(cs[ni][0] - nm0);
            cs[ni][1] = __expf(cs[ni][1] - nm0);
            cs[ni][2] = __expf(cs[ni][2] - nm1);
            cs[ni][3] = __expf(cs[ni][3] - nm1);
            ts0 += cs[ni][0] + cs[ni][1];
            ts1 += cs[ni][2] + cs[ni][3];
        }
        ts0 += __shfl_xor_sync(0xffffffffu, ts0, 1);
        ts0 += __shfl_xor_sync(0xffffffffu, ts0, 2);
        ts1 += __shfl_xor_sync(0xffffffffu, ts1, 1);
        ts1 += __shfl_xor_sync(0xffffffffu, ts1, 2);
        l_r[0] = l_r[0] * a0 + ts0;
        l_r[1] = l_r[1] * a1 + ts1;
        m_r[0] = nm0;
        m_r[1] = nm1;
        #pragma unroll
        for (int ni = 0; ni < 8; ni++) {
            co[ni][0] *= a0; co[ni][1] *= a0;
            co[ni][2] *= a1; co[ni][3] *= a1;
        }

        // ---- O += P @ V: A-frags via 4-lane shfl permute ----
        #pragma unroll
        for (int kc = 0; kc < 16; kc++) {
            float v00 = __shfl_sync(0xffffffffu, cs[kc][0], srcA);
            float v01 = __shfl_sync(0xffffffffu, cs[kc][1], srcA);
            float v10 = __shfl_sync(0xffffffffu, cs[kc][2], srcA);
            float v11 = __shfl_sync(0xffffffffu, cs[kc][3], srcA);
            float v20 = __shfl_sync(0xffffffffu, cs[kc][0], srcB);
            float v21 = __shfl_sync(0xffffffffu, cs[kc][1], srcB);
            float v30 = __shfl_sync(0xffffffffu, cs[kc][2], srcB);
            float v31 = __shfl_sync(0xffffffffu, cs[kc][3], srcB);
            unsigned af[4];
            af[0] = __float_as_uint(f2tf(odd ? v01 : v00));
            af[1] = __float_as_uint(f2tf(odd ? v11 : v10));
            af[2] = __float_as_uint(f2tf(odd ? v21 : v20));
            af[3] = __float_as_uint(f2tf(odd ? v31 : v30));
            int kk = kc * 8;
            #pragma unroll
            for (int ni = 0; ni < 8; ni++) {
                unsigned bf[2];
                int n = ni * 8 + gid;
                bf[0] = __float_as_uint(Vc[(kk + tig) * FP + n]);
                bf[1] = __float_as_uint(Vc[(kk + tig + 4) * FP + n]);
                mma_tf32(co[ni], af, bf);
            }
        }
    }

    {
        float inv0 = 1.f / l_r[0];
        float inv1 = 1.f / l_r[1];
        int r0 = bm + wm + gid;
        #pragma unroll
        for (int ni = 0; ni < 8; ni++) {
            int col = ni * 8 + tig * 2;
            *(float2*)&Cp[(size_t)r0 * ND + col] =
                make_float2(f2tf(co[ni][0] * inv0), f2tf(co[ni][1] * inv0));
            *(float2*)&Cp[(size_t)(r0 + 8) * ND + col] =
                make_float2(f2tf(co[ni][2] * inv1), f2tf(co[ni][3] * inv1));
        }
    }
}

// ---------------- launch ----------------
extern "C" void kernel_launch(void* const* d_in, const int* in_sizes, int n_in,
                              void* d_out, int out_size) {
    const int*   src    = (const int*)d_in[0];
    const int*   dst    = (const int*)d_in[1];
    const float* w1     = (const float*)d_in[2];
    const float* b1     = (const float*)d_in[3];
    const float* w2     = (const float*)d_in[4];
    const float* b2     = (const float*)d_in[5];
    const float* proj_w = (const float*)d_in[6];
    const float* proj_b = (const float*)d_in[7];
    const float* ln1_g  = (const float*)d_in[8];
    const float* ln1_b  = (const float*)d_in[9];
    const float* w_qkv  = (const float*)d_in[10];
    const float* b_qkv  = (const float*)d_in[11];
    const float* w_o    = (const float*)d_in[12];
    const float* b_o    = (const float*)d_in[13];
    const float* ln2_g  = (const float*)d_in[14];
    const float* ln2_b  = (const float*)d_in[15];
    const float* w_ff1  = (const float*)d_in[16];
    const float* b_ff1  = (const float*)d_in[17];
    const float* w_ff2  = (const float*)d_in[18];
    const float* b_ff2  = (const float*)d_in[19];
    float* out = (float*)d_out;

    cudaFuncSetAttribute(flash_tf32, cudaFuncAttributeMaxDynamicSharedMemorySize, SM_TOT);
    cudaFuncSetAttribute(gemm_tf32, cudaFuncAttributeMaxDynamicSharedMemorySize, GEMM_SMEM);
    cudaFuncSetAttribute(gemm_wo_ln, cudaFuncAttributeMaxDynamicSharedMemorySize, GEMM_SMEM);

    float* WR;
    {
        void* p; cudaGetSymbolAddress(&p, g_WR); WR = (float*)p;
    }

    k_rnd_all<<<196608 / 256, 256>>>(w_qkv, w_o, w_ff1, w_ff2);
    k_Wb<<<ND + 1, ND>>>(w2, proj_w, b2, proj_b);
    k_table<<<513, ND>>>(w1, b1);
    k_cooc<<<2 * NB, 256>>>(src, dst);
    k_featln<<<NTOK, ND>>>(ln1_g, ln1_b);

    // transformer (both streams batched: 65536 tokens)
    gemm_tf32<<<dim3(3, NTOK / 128), 256, GEMM_SMEM>>>(BUF_H, WR + WR_QKV, b_qkv, -1,
        BUF_QKV, nullptr, NTOK, 384, 128, 0, 1, 1);
    flash_tf32<<<dim3(NL / 128, NHB), 256, SM_TOT>>>();
    gemm_wo_ln<<<NTOK / 128, 256, GEMM_SMEM>>>(WR + WR_WO, b_o, ln2_g, ln2_b);
    gemm_tf32<<<dim3(4, NTOK / 128), 256, GEMM_SMEM>>>(BUF_H, WR + WR_FF1, b_ff1, -1,
        BUF_FF, nullptr, NTOK, 512, 128, 1, 1, 0);
    gemm_tf32<<<dim3(1, NTOK / 128), 256, GEMM_SMEM>>>(BUF_FF, WR + WR_FF2, b_ff2, BUF_X,
        BUF_X, out, NTOK, 128, 512, 0, 0, 0);
}

// round 16
// speedup vs baseline: 1.1131x; 1.0346x over previous
#include <cuda_runtime.h>
#include <math.h>

#define NB    64
#define NL    512
#define ND    128
#define TOKS  32768
#define NTOK  65536
#define NHB   256

// ---------------- scratch ----------------
__device__ int   g_cnt[NTOK * 2];
__device__ float g_W[ND * ND];
__device__ float g_biasT[ND];
__device__ float g_T2[513 * ND];
__device__ float g_X[(size_t)NTOK * ND];
__device__ float g_H[(size_t)NTOK * ND];
__device__ float g_QKV[(size_t)NTOK * 3 * ND];
__device__ float g_CTX[(size_t)NTOK * ND];
__device__ float g_FF[(size_t)NTOK * 4 * ND];
__device__ float g_WR[196608];   // pre-rounded weights: QKV | WO | FF1 | FF2

#define WR_QKV 0
#define WR_WO  49152
#define WR_FF1 65536
#define WR_FF2 131072

#define BUF_X    0
#define BUF_H    1
#define BUF_QKV  2
#define BUF_CTX  3
#define BUF_FF   4
__device__ __forceinline__ float* buf(int id) {
    switch (id) {
        case BUF_X:   return g_X;
        case BUF_H:   return g_H;
        case BUF_QKV: return g_QKV;
        case BUF_CTX: return g_CTX;
        default:      return g_FF;
    }
}

__device__ __forceinline__ float f2tf(float x) {
    unsigned r;
    asm("cvt.rna.tf32.f32 %0, %1;" : "=r"(r) : "f"(x));
    return __uint_as_float(r);
}

__device__ __forceinline__ void mma_tf32(float* c, const unsigned* a, const unsigned* b) {
    asm volatile(
        "mma.sync.aligned.m16n8k8.row.col.f32.tf32.tf32.f32 "
        "{%0,%1,%2,%3}, {%4,%5,%6,%7}, {%8,%9}, {%0,%1,%2,%3};"
        : "+f"(c[0]), "+f"(c[1]), "+f"(c[2]), "+f"(c[3])
        : "r"(a[0]), "r"(a[1]), "r"(a[2]), "r"(a[3]), "r"(b[0]), "r"(b[1]));
}

__device__ __forceinline__ void cp_async16(float* smem_dst, const float* gsrc) {
    unsigned saddr = (unsigned)__cvta_generic_to_shared(smem_dst);
    asm volatile("cp.async.cg.shared.global [%0], [%1], 16;" :: "r"(saddr), "l"(gsrc));
}

__device__ __forceinline__ float gelu_f(float x) {
    float z  = x * 0.70710678118654752f;
    float az = fabsf(z);
    float t  = __fdividef(1.f, fmaf(0.3275911f, az, 1.f));
    float p  = t * (0.254829592f + t * (-0.284496736f + t * (1.421413741f +
               t * (-1.453152027f + t * 1.061405429f))));
    float er = copysignf(1.f - p * __expf(-z * z), z);
    return 0.5f * x * (1.f + er);
}

// ---------------- precompute kernels ----------------
__global__ void k_rnd_all(const float* __restrict__ qkv, const float* __restrict__ wo,
                          const float* __restrict__ ff1, const float* __restrict__ ff2) {
    int i = blockIdx.x * 256 + threadIdx.x;
    const float* s; int off;
    if (i < 49152)        { s = qkv; off = i; }
    else if (i < 65536)   { s = wo;  off = i - 49152; }
    else if (i < 131072)  { s = ff1; off = i - 65536; }
    else                  { s = ff2; off = i - 131072; }
    g_WR[i] = f2tf(s[off]);
}

__global__ void k_Wb(const float* __restrict__ w2, const float* __restrict__ proj_w,
                     const float* __restrict__ b2, const float* __restrict__ proj_b) {
    int d = threadIdx.x;
    if (blockIdx.x < ND) {
        int k = blockIdx.x;
        float acc = 0.f;
        #pragma unroll 8
        for (int j = 0; j < ND; j++) acc += w2[k * ND + j] * proj_w[j * ND + d];
        g_W[k * ND + d] = acc;
    } else {
        float acc = proj_b[d];
        #pragma unroll 8
        for (int k = 0; k < ND; k++) acc += 2.f * b2[k] * proj_w[k * ND + d];
        g_biasT[d] = acc;
    }
}

__global__ void k_table(const float* __restrict__ w1, const float* __restrict__ b1) {
    __shared__ float h[ND];
    int c = blockIdx.x, d = threadIdx.x;
    h[d] = fmaxf((float)c * w1[d] + b1[d], 0.f);
    __syncthreads();
    float acc = 0.5f * g_biasT[d];
    #pragma unroll 8
    for (int k = 0; k < ND; k++) acc += h[k] * g_W[k * ND + d];
    g_T2[c * ND + d] = acc;
}

__global__ void k_cooc(const int* __restrict__ src, const int* __restrict__ dst) {
    __shared__ int ss[NL], dd[NL];
    int blk = blockIdx.x;
    int b = blk >> 1, half = blk & 1;
    int tid = threadIdx.x;
    for (int idx = tid; idx < NL; idx += 256) {
        ss[idx] = src[b * NL + idx];
        dd[idx] = dst[b * NL + idx];
    }
    __syncthreads();
    int i = half * 256 + tid;
    int qs = ss[i], qd = dd[i];
    int css = 0, csd = 0, cds = 0, cdd = 0;
    #pragma unroll 8
    for (int j = 0; j < NL; j++) {
        int s = ss[j], t = dd[j];
        css += (qs == s); csd += (qs == t);
        cds += (qd == s); cdd += (qd == t);
    }
    if (qs == 0) { css = 0; csd = 0; }
    if (qd == 0) { cds = 0; cdd = 0; }
    int ts = b * NL + i, td = TOKS + b * NL + i;
    g_cnt[ts * 2 + 0] = css; g_cnt[ts * 2 + 1] = csd;
    g_cnt[td * 2 + 0] = cds; g_cnt[td * 2 + 1] = cdd;
}

__global__ void k_featln(const float* __restrict__ g, const float* __restrict__ b) {
    int row = blockIdx.x, t = threadIdx.x;
    int c0 = g_cnt[row * 2], c1 = g_cnt[row * 2 + 1];
    float v = g_T2[c0 * ND + t] + g_T2[c1 * ND + t];
    g_X[(size_t)row * ND + t] = v;
    __shared__ float sh[4];
    float s = v;
    for (int o = 16; o; o >>= 1) s += __shfl_xor_sync(0xffffffffu, s, o);
    int w = t >> 5;
    if ((t & 31) == 0) sh[w] = s;
    __syncthreads();
    float mu = (sh[0] + sh[1] + sh[2] + sh[3]) * (1.f / 128.f);
    __syncthreads();
    float dlt = v - mu;
    float s2 = dlt * dlt;
    for (int o = 16; o; o >>= 1) s2 += __shfl_xor_sync(0xffffffffu, s2, o);
    if ((t & 31) == 0) sh[w] = s2;
    __syncthreads();
    float var = (sh[0] + sh[1] + sh[2] + sh[3]) * (1.f / 128.f);
    float r = rsqrtf(var + 1e-5f);
    g_H[(size_t)row * ND + t] = f2tf(dlt * r * g[t] + b[t]);
}

// ============ tf32 GEMM, 3-stage cp.async (128x128 tile, occ 2) ============
#define AP 20
#define BP 136
#define NSTG 3
#define GEMM_SMEM ((NSTG * 128 * AP + NSTG * 16 * BP) * 4)
__global__ __launch_bounds__(256, 2) void gemm_tf32(
        int Aid, const float* __restrict__ Bm,
        const float* __restrict__ bias, int resid,
        int Cid, float* __restrict__ cext,
        int M, int N, int K, int act, int rndC, int kscale) {
    const float* A = buf(Aid);
    const float* res = (resid >= 0) ? buf(resid) : nullptr;
    float* C = cext ? cext : buf(Cid);
    extern __shared__ float gsm[];
    float* Asm = gsm;
    float* Bsm = gsm + NSTG * 128 * AP;
    int tid = threadIdx.x;
    int lane = tid & 31, warp = tid >> 5;
    int wm = (warp >> 1) * 32, wn = (warp & 1) * 64;
    int gid = lane >> 2, tig = lane & 3;
    int bm = blockIdx.y * 128, bn = blockIdx.x * 128;

    int a_row = tid >> 1, a_kc = (tid & 1) * 8;
    int b_row = tid >> 4, b_nc = (tid & 15) * 8;

    int nk = K / 16;
    #pragma unroll
    for (int p = 0; p < 2; p++) {
        if (p < nk) {
            int k0 = p * 16;
            const float* ga = &A[(size_t)(bm + a_row) * K + k0 + a_kc];
            cp_async16(&Asm[p * 128 * AP + a_row * AP + a_kc], ga);
            cp_async16(&Asm[p * 128 * AP + a_row * AP + a_kc + 4], ga + 4);
            const float* gb = &Bm[(size_t)(k0 + b_row) * N + bn + b_nc];
            cp_async16(&Bsm[p * 16 * BP + b_row * BP + b_nc], gb);
            cp_async16(&Bsm[p * 16 * BP + b_row * BP + b_nc + 4], gb + 4);
            asm volatile("cp.async.commit_group;");
        }
    }

    float acc[2][8][4] = {};
    for (int it = 0; it < nk; it++) {
        if (it + 1 < nk) asm volatile("cp.async.wait_group 1;");
        else             asm volatile("cp.async.wait_group 0;");
        __syncthreads();
        if (it + 2 < nk) {
            int nxt = (it + 2) % NSTG, k0 = (it + 2) * 16;
            const float* ga = &A[(size_t)(bm + a_row) * K + k0 + a_kc];
            cp_async16(&Asm[nxt * 128 * AP + a_row * AP + a_kc], ga);
            cp_async16(&Asm[nxt * 128 * AP + a_row * AP + a_kc + 4], ga + 4);
            const float* gb = &Bm[(size_t)(k0 + b_row) * N + bn + b_nc];
            cp_async16(&Bsm[nxt * 16 * BP + b_row * BP + b_nc], gb);
            cp_async16(&Bsm[nxt * 16 * BP + b_row * BP + b_nc + 4], gb + 4);
            asm volatile("cp.async.commit_group;");
        }
        const float* As = Asm + (it % NSTG) * 128 * AP;
        const float* Bs = Bsm + (it % NSTG) * 16 * BP;
        #pragma unroll
        for (int kk = 0; kk < 16; kk += 8) {
            unsigned af[2][4], bf[8][2];
            #pragma unroll
            for (int mi = 0; mi < 2; mi++) {
                int mb = wm + mi * 16 + gid;
                af[mi][0] = __float_as_uint(As[mb * AP + kk + tig]);
                af[mi][1] = __float_as_uint(As[(mb + 8) * AP + kk + tig]);
                af[mi][2] = __float_as_uint(As[mb * AP + kk + tig + 4]);
                af[mi][3] = __float_as_uint(As[(mb + 8) * AP + kk + tig + 4]);
            }
            #pragma unroll
            for (int ni = 0; ni < 8; ni++) {
                int n = wn + ni * 8 + gid;
                bf[ni][0] = __float_as_uint(Bs[(kk + tig) * BP + n]);
                bf[ni][1] = __float_as_uint(Bs[(kk + tig + 4) * BP + n]);
            }
            #pragma unroll
            for (int mi = 0; mi < 2; mi++)
                #pragma unroll
                for (int ni = 0; ni < 8; ni++)
                    mma_tf32(acc[mi][ni], af[mi], bf[ni]);
        }
    }

    #pragma unroll
    for (int mi = 0; mi < 2; mi++) {
        int r0 = bm + wm + mi * 16 + gid;
        #pragma unroll
        for (int ni = 0; ni < 8; ni++) {
            int col = bn + wn + ni * 8 + tig * 2;
            float x0 = acc[mi][ni][0], x1 = acc[mi][ni][1];
            float x2 = acc[mi][ni][2], x3 = acc[mi][ni][3];
            if (bias) {
                float bb0 = bias[col], bb1 = bias[col + 1];
                x0 += bb0; x1 += bb1; x2 += bb0; x3 += bb1;
            }
            if (kscale && col >= 128 && col < 256) {
                x0 *= 0.125f; x1 *= 0.125f; x2 *= 0.125f; x3 *= 0.125f;
            }
            if (act) {
                x0 = gelu_f(x0); x1 = gelu_f(x1);
                x2 = gelu_f(x2); x3 = gelu_f(x3);
            }
            if (rndC) {
                x0 = f2tf(x0); x1 = f2tf(x1); x2 = f2tf(x2); x3 = f2tf(x3);
            }
            if (res) {
                x0 += res[(size_t)r0 * N + col];       x1 += res[(size_t)r0 * N + col + 1];
                x2 += res[(size_t)(r0 + 8) * N + col]; x3 += res[(size_t)(r0 + 8) * N + col + 1];
            }
            *(float2*)&C[(size_t)r0 * N + col] = make_float2(x0, x1);
            *(float2*)&C[(size_t)(r0 + 8) * N + col] = make_float2(x2, x3);
        }
    }
}

// ============ WO GEMM + residual + fused LN2 ============
__global__ __launch_bounds__(256, 2) void gemm_wo_ln(
        const float* __restrict__ Bm, const float* __restrict__ bias,
        const float* __restrict__ lng, const float* __restrict__ lnb) {
    const float* A = g_CTX;
    extern __shared__ float gsm[];
    float* Asm = gsm;
    float* Bsm = gsm + NSTG * 128 * AP;
    int tid = threadIdx.x;
    int lane = tid & 31, warp = tid >> 5;
    int wm = (warp >> 1) * 32, wn = (warp & 1) * 64;
    int gid = lane >> 2, tig = lane & 3;
    int bm = blockIdx.x * 128;

    int a_row = tid >> 1, a_kc = (tid & 1) * 8;
    int b_row = tid >> 4, b_nc = (tid & 15) * 8;

    const int nk = 8;
    #pragma unroll
    for (int p = 0; p < 2; p++) {
        int k0 = p * 16;
        const float* ga = &A[(size_t)(bm + a_row) * 128 + k0 + a_kc];
        cp_async16(&Asm[p * 128 * AP + a_row * AP + a_kc], ga);
        cp_async16(&Asm[p * 128 * AP + a_row * AP + a_kc + 4], ga + 4);
        const float* gb = &Bm[(size_t)(k0 + b_row) * 128 + b_nc];
        cp_async16(&Bsm[p * 16 * BP + b_row * BP + b_nc], gb);
        cp_async16(&Bsm[p * 16 * BP + b_row * BP + b_nc + 4], gb + 4);
        asm volatile("cp.async.commit_group;");
    }

    float acc[2][8][4] = {};
    for (int it = 0; it < nk; it++) {
        if (it + 1 < nk) asm volatile("cp.async.wait_group 1;");
        else             asm volatile("cp.async.wait_group 0;");
        __syncthreads();
        if (it + 2 < nk) {
            int nxt = (it + 2) % NSTG, k0 = (it + 2) * 16;
            const float* ga = &A[(size_t)(bm + a_row) * 128 + k0 + a_kc];
            cp_async16(&Asm[nxt * 128 * AP + a_row * AP + a_kc], ga);
            cp_async16(&Asm[nxt * 128 * AP + a_row * AP + a_kc + 4], ga + 4);
            const float* gb = &Bm[(size_t)(k0 + b_row) * 128 + b_nc];
            cp_async16(&Bsm[nxt * 16 * BP + b_row * BP + b_nc], gb);
            cp_async16(&Bsm[nxt * 16 * BP + b_row * BP + b_nc + 4], gb + 4);
            asm volatile("cp.async.commit_group;");
        }
        const float* As = Asm + (it % NSTG) * 128 * AP;
        const float* Bs = Bsm + (it % NSTG) * 16 * BP;
        #pragma unroll
        for (int kk = 0; kk < 16; kk += 8) {
            unsigned af[2][4], bf[8][2];
            #pragma unroll
            for (int mi = 0; mi < 2; mi++) {
                int mb = wm + mi * 16 + gid;
                af[mi][0] = __float_as_uint(As[mb * AP + kk + tig]);
                af[mi][1] = __float_as_uint(As[(mb + 8) * AP + kk + tig]);
                af[mi][2] = __float_as_uint(As[mb * AP + kk + tig + 4]);
                af[mi][3] = __float_as_uint(As[(mb + 8) * AP + kk + tig + 4]);
            }
            #pragma unroll
            for (int ni = 0; ni < 8; ni++) {
                int n = wn + ni * 8 + gid;
                bf[ni][0] = __float_as_uint(Bs[(kk + tig) * BP + n]);
                bf[ni][1] = __float_as_uint(Bs[(kk + tig + 4) * BP + n]);
            }
            #pragma unroll
            for (int mi = 0; mi < 2; mi++)
                #pragma unroll
                for (int ni = 0; ni < 8; ni++)
                    mma_tf32(acc[mi][ni], af[mi], bf[ni]);
        }
    }

    #pragma unroll
    for (int mi = 0; mi < 2; mi++) {
        int r0 = bm + wm + mi * 16 + gid;
        #pragma unroll
        for (int ni = 0; ni < 8; ni++) {
            int col = wn + ni * 8 + tig * 2;
            float bb0 = bias[col], bb1 = bias[col + 1];
            acc[mi][ni][0] += bb0 + g_X[(size_t)r0 * ND + col];
            acc[mi][ni][1] += bb1 + g_X[(size_t)r0 * ND + col + 1];
            acc[mi][ni][2] += bb0 + g_X[(size_t)(r0 + 8) * ND + col];
            acc[mi][ni][3] += bb1 + g_X[(size_t)(r0 + 8) * ND + col + 1];
        }
    }
    __syncthreads();
    float2* ps = (float2*)gsm;
    #pragma unroll
    for (int mi = 0; mi < 2; mi++) {
        float sA = 0.f, qA = 0.f, sB = 0.f, qB = 0.f;
        #pragma unroll
        for (int ni = 0; ni < 8; ni++) {
            float x0 = acc[mi][ni][0], x1 = acc[mi][ni][1];
            float x2 = acc[mi][ni][2], x3 = acc[mi][ni][3];
            sA += x0 + x1;  qA += x0 * x0 + x1 * x1;
            sB += x2 + x3;  qB += x2 * x2 + x3 * x3;
        }
        #pragma unroll
        for (int o = 1; o <= 2; o <<= 1) {
            sA += __shfl_xor_sync(0xffffffffu, sA, o);
            qA += __shfl_xor_sync(0xffffffffu, qA, o);
            sB += __shfl_xor_sync(0xffffffffu, sB, o);
            qB += __shfl_xor_sync(0xffffffffu, qB, o);
        }
        if (tig == 0) {
            int lr = wm + mi * 16 + gid;
            ps[lr * 2 + (warp & 1)] = make_float2(sA, qA);
            ps[(lr + 8) * 2 + (warp & 1)] = make_float2(sB, qB);
        }
    }
    __syncthreads();
    #pragma unroll
    for (int mi = 0; mi < 2; mi++) {
        int lr = wm + mi * 16 + gid;
        float2 pa = ps[lr * 2], pb = ps[lr * 2 + 1];
        float mu0 = (pa.x + pb.x) * (1.f / 128.f);
        float v0  = fmaxf((pa.y + pb.y) * (1.f / 128.f) - mu0 * mu0, 0.f);
        float rv0 = rsqrtf(v0 + 1e-5f);
        float2 pc = ps[(lr + 8) * 2], pd = ps[(lr + 8) * 2 + 1];
        float mu1 = (pc.x + pd.x) * (1.f / 128.f);
        float v1  = fmaxf((pc.y + pd.y) * (1.f / 128.f) - mu1 * mu1, 0.f);
        float rv1 = rsqrtf(v1 + 1e-5f);
        int r0 = bm + lr;
        #pragma unroll
        for (int ni = 0; ni < 8; ni++) {
            int col = wn + ni * 8 + tig * 2;
            float g0 = lng[col], g1 = lng[col + 1];
            float b0 = lnb[col], b1 = lnb[col + 1];
            float x0 = acc[mi][ni][0], x1 = acc[mi][ni][1];
            float x2 = acc[mi][ni][2], x3 = acc[mi][ni][3];
            *(float2*)&g_X[(size_t)r0 * ND + col] = make_float2(x0, x1);
            *(float2*)&g_X[(size_t)(r0 + 8) * ND + col] = make_float2(x2, x3);
            *(float2*)&g_H[(size_t)r0 * ND + col] =
                make_float2(f2tf((x0 - mu0) * rv0 * g0 + b0),
                            f2tf((x1 - mu0) * rv0 * g1 + b1));
            *(float2*)&g_H[(size_t)(r0 + 8) * ND + col] =
                make_float2(f2tf((x2 - mu1) * rv1 * g0 + b0),
                            f2tf((x3 - mu1) * rv1 * g1 + b1));
        }
    }
}

// ============ flash attention: 128-row Q block, 64-key tiles, occ 2 ============
// CTA: 256 threads = 8 warps x 16 rows. K/V double-buffered 64-key tiles.
// SMEM = Q(128x68) + 2*K(64x68) + 2*V(64x68) = 102 KB -> 2 CTAs/SM.
#define FP 68
#define FQ 0
#define FK (128 * FP)
#define FV (FK + 2 * 64 * FP)
#define SM_TOT ((FV + 2 * 64 * FP) * 4)

__global__ __launch_bounds__(256, 2) void flash_tf32() {
    extern __shared__ float sm[];
    float* Qs = sm + FQ;
    float* Ks = sm + FK;   // [2][64*FP]
    float* Vs = sm + FV;   // [2][64*FP]

    int z = blockIdx.y;
    int sb = z >> 1, h = z & 1;
    const float* Qp = g_QKV + (size_t)sb * NL * 384 + h * 64;
    const float* Kp = Qp + 128;
    const float* Vp = Qp + 256;
    float* Cp = g_CTX + (size_t)sb * NL * ND + h * 64;

    int bm = blockIdx.x * 128;
    int tid = threadIdx.x, lane = tid & 31, warp = tid >> 5;
    int wm = warp * 16;
    int gid = lane >> 2, tig = lane & 3;
    int srcA = (lane & ~3) | (tig >> 1);
    int srcB = srcA | 2;
    bool odd = tig & 1;

    // prologue: Q (128 rows) + K0/V0 (64 rows each)
    {
        int qr = tid >> 1, qc = (tid & 1) * 32;
        #pragma unroll
        for (int i = 0; i < 8; i++)
            cp_async16(&Qs[qr * FP + qc + i * 4],
                       &Qp[(size_t)(bm + qr) * 384 + qc + i * 4]);
        int kr = tid >> 2, kc4 = (tid & 3) * 16;
        #pragma unroll
        for (int i = 0; i < 4; i++)
            cp_async16(&Ks[kr * FP + kc4 + i * 4],
                       &Kp[(size_t)kr * 384 + kc4 + i * 4]);
        #pragma unroll
        for (int i = 0; i < 4; i++)
            cp_async16(&Vs[kr * FP + kc4 + i * 4],
                       &Vp[(size_t)kr * 384 + kc4 + i * 4]);
        asm volatile("cp.async.commit_group;");
    }

    unsigned aq[8][4];                 // Q fragments, persist across all tiles
    float co[8][4] = {};
    float m_r[2] = {-1e30f, -1e30f};
    float l_r[2] = {0.f, 0.f};

    for (int t = 0; t < 8; t++) {
        asm volatile("cp.async.wait_group 0;");
        __syncthreads();   // tile t visible; buffer (t+1)&1 fully consumed (tile t-1)
        if (t == 0) {
            int mb = wm + gid;
            #pragma unroll
            for (int kc = 0; kc < 8; kc++) {
                int kk = kc * 8;
                aq[kc][0] = __float_as_uint(Qs[mb * FP + kk + tig]);
                aq[kc][1] = __float_as_uint(Qs[(mb + 8) * FP + kk + tig]);
                aq[kc][2] = __float_as_uint(Qs[mb * FP + kk + tig + 4]);
                aq[kc][3] = __float_as_uint(Qs[(mb + 8) * FP + kk + tig + 4]);
            }
        }
        if (t + 1 < 8) {
            int nb = (t + 1) & 1;
            int kr = tid >> 2, kc4 = (tid & 3) * 16;
            int grow = (t + 1) * 64 + kr;
            #pragma unroll
            for (int i = 0; i < 4; i++)
                cp_async16(&Ks[nb * 64 * FP + kr * FP + kc4 + i * 4],
                           &Kp[(size_t)grow * 384 + kc4 + i * 4]);
            #pragma unroll
            for (int i = 0; i < 4; i++)
                cp_async16(&Vs[nb * 64 * FP + kr * FP + kc4 + i * 4],
                           &Vp[(size_t)grow * 384 + kc4 + i * 4]);
            asm volatile("cp.async.commit_group;");
        }
        const float* Kc = Ks + (t & 1) * 64 * FP;
        const float* Vc = Vs + (t & 1) * 64 * FP;

        // ---- S = Q @ K'^T (warp tile 16 x 64) ----
        float cs[8][4] = {};
        #pragma unroll
        for (int kc = 0; kc < 8; kc++) {
            int kk = kc * 8;
            #pragma unroll
            for (int ni = 0; ni < 8; ni++) {
                unsigned bf[2];
                int n = ni * 8 + gid;
                bf[0] = __float_as_uint(Kc[n * FP + kk + tig]);
                bf[1] = __float_as_uint(Kc[n * FP + kk + tig + 4]);
                mma_tf32(cs[ni], aq[kc], bf);
            }
        }

        // ---- online softmax (rows fully inside warp) ----
        float tm0 = -1e30f, tm1 = -1e30f;
        #pragma unroll
        for (int ni = 0; ni < 8; ni++) {
            tm0 = fmaxf(tm0, fmaxf(cs[ni][0], cs[ni][1]));
            tm1 = fmaxf(tm1, fmaxf(cs[ni][2], cs[ni][3]));
        }
        tm0 = fmaxf(tm0, __shfl_xor_sync(0xffffffffu, tm0, 1));
        tm0 = fmaxf(tm0, __shfl_xor_sync(0xffffffffu, tm0, 2));
        tm1 = fmaxf(tm1, __shfl_xor_sync(0xffffffffu, tm1, 1));
        tm1 = fmaxf(tm1, __shfl_xor_sync(0xffffffffu, tm1, 2));
        float nm0 = fmaxf(m_r[0], tm0);
        float nm1 = fmaxf(m_r[1], tm1);
        float a0 = __expf(m_r[0] - nm0);
        float a1 = __expf(m_r[1] - nm1);
        float ts0 = 0.f, ts1 = 0.f;
        #pragma unroll
        for (int ni = 0; ni < 8; ni++) {
            cs[ni][0] = __expf(cs[ni][0] - nm0);
            cs[ni][1] = __expf(cs[ni][1] - nm0);
            cs[ni][2] = __expf(cs[ni][2] - nm1);
            cs[ni][3] = __expf(cs[ni][3] - nm1);
            ts0 += cs[ni][0] + cs[ni][1];
            ts1 += cs[ni][2] + cs[ni][3];
        }
        ts0 += __shfl_xor_sync(0xffffffffu, ts0, 1);
        ts0 += __shfl_xor_sync(0xffffffffu, ts0, 2);
        ts1 += __shfl_xor_sync(0xffffffffu, ts1, 1);
        ts1 += __shfl_xor_sync(0xffffffffu, ts1, 2);
        l_r[0] = l_r[0] * a0 + ts0;
        l_r[1] = l_r[1] * a1 + ts1;
        m_r[0] = nm0;
        m_r[1] = nm1;
        #pragma unroll
        for (int ni = 0; ni < 8; ni++) {
            co[ni][0] *= a0; co[ni][1] *= a0;
            co[ni][2] *= a1; co[ni][3] *= a1;
        }

        // ---- O += P @ V: A-frags via 4-lane shfl permute (keys 0..63) ----
        #pragma unroll
        for (int kc = 0; kc < 8; kc++) {
            float v00 = __shfl_sync(0xffffffffu, cs[kc][0], srcA);
            float v01 = __shfl_sync(0xffffffffu, cs[kc][1], srcA);
            float v10 = __shfl_sync(0xffffffffu, cs[kc][2], srcA);
            float v11 = __shfl_sync(0xffffffffu, cs[kc][3], srcA);
            float v20 = __shfl_sync(0xffffffffu, cs[kc][0], srcB);
            float v21 = __shfl_sync(0xffffffffu, cs[kc][1], srcB);
            float v30 = __shfl_sync(0xffffffffu, cs[kc][2], srcB);
            float v31 = __shfl_sync(0xffffffffu, cs[kc][3], srcB);
            unsigned af[4];
            af[0] = __float_as_uint(f2tf(odd ? v01 : v00));
            af[1] = __float_as_uint(f2tf(odd ? v11 : v10));
            af[2] = __float_as_uint(f2tf(odd ? v21 : v20));
            af[3] = __float_as_uint(f2tf(odd ? v31 : v30));
            int kk = kc * 8;
            #pragma unroll
            for (int ni = 0; ni < 8; ni++) {
                unsigned bf[2];
                int n = ni * 8 + gid;
                bf[0] = __float_as_uint(Vc[(kk + tig) * FP + n]);
                bf[1] = __float_as_uint(Vc[(kk + tig + 4) * FP + n]);
                mma_tf32(co[ni], af, bf);
            }
        }
    }

    {
        float inv0 = 1.f / l_r[0];
        float inv1 = 1.f / l_r[1];
        int r0 = bm + wm + gid;
        #pragma unroll
        for (int ni = 0; ni < 8; ni++) {
            int col = ni * 8 + tig * 2;
            *(float2*)&Cp[(size_t)r0 * ND + col] =
                make_float2(f2tf(co[ni][0] * inv0), f2tf(co[ni][1] * inv0));
            *(float2*)&Cp[(size_t)(r0 + 8) * ND + col] =
                make_float2(f2tf(co[ni][2] * inv1), f2tf(co[ni][3] * inv1));
        }
    }
}

// ---------------- launch ----------------
extern "C" void kernel_launch(void* const* d_in, const int* in_sizes, int n_in,
                              void* d_out, int out_size) {
    const int*   src    = (const int*)d_in[0];
    const int*   dst    = (const int*)d_in[1];
    const float* w1     = (const float*)d_in[2];
    const float* b1     = (const float*)d_in[3];
    const float* w2     = (const float*)d_in[4];
    const float* b2     = (const float*)d_in[5];
    const float* proj_w = (const float*)d_in[6];
    const float* proj_b = (const float*)d_in[7];
    const float* ln1_g  = (const float*)d_in[8];
    const float* ln1_b  = (const float*)d_in[9];
    const float* w_qkv  = (const float*)d_in[10];
    const float* b_qkv  = (const float*)d_in[11];
    const float* w_o    = (const float*)d_in[12];
    const float* b_o    = (const float*)d_in[13];
    const float* ln2_g  = (const float*)d_in[14];
    const float* ln2_b  = (const float*)d_in[15];
    const float* w_ff1  = (const float*)d_in[16];
    const float* b_ff1  = (const float*)d_in[17];
    const float* w_ff2  = (const float*)d_in[18];
    const float* b_ff2  = (const float*)d_in[19];
    float* out = (float*)d_out;

    cudaFuncSetAttribute(flash_tf32, cudaFuncAttributeMaxDynamicSharedMemorySize, SM_TOT);
    cudaFuncSetAttribute(gemm_tf32, cudaFuncAttributeMaxDynamicSharedMemorySize, GEMM_SMEM);
    cudaFuncSetAttribute(gemm_wo_ln, cudaFuncAttributeMaxDynamicSharedMemorySize, GEMM_SMEM);

    float* WR;
    {
        void* p; cudaGetSymbolAddress(&p, g_WR); WR = (float*)p;
    }

    k_rnd_all<<<196608 / 256, 256>>>(w_qkv, w_o, w_ff1, w_ff2);
    k_Wb<<<ND + 1, ND>>>(w2, proj_w, b2, proj_b);
    k_table<<<513, ND>>>(w1, b1);
    k_cooc<<<2 * NB, 256>>>(src, dst);
    k_featln<<<NTOK, ND>>>(ln1_g, ln1_b);

    // transformer (both streams batched: 65536 tokens)
    gemm_tf32<<<dim3(3, NTOK / 128), 256, GEMM_SMEM>>>(BUF_H, WR + WR_QKV, b_qkv, -1,
        BUF_QKV, nullptr, NTOK, 384, 128, 0, 1, 1);
    flash_tf32<<<dim3(NL / 128, NHB), 256, SM_TOT>>>();
    gemm_wo_ln<<<NTOK / 128, 256, GEMM_SMEM>>>(WR + WR_WO, b_o, ln2_g, ln2_b);
    gemm_tf32<<<dim3(4, NTOK / 128), 256, GEMM_SMEM>>>(BUF_H, WR + WR_FF1, b_ff1, -1,
        BUF_FF, nullptr, NTOK, 512, 128, 1, 1, 0);
    gemm_tf32<<<dim3(1, NTOK / 128), 256, GEMM_SMEM>>>(BUF_FF, WR + WR_FF2, b_ff2, BUF_X,
        BUF_X, out, NTOK, 128, 512, 0, 0, 0);
}